// round 6
// baseline (speedup 1.0000x reference)
#include <cuda_runtime.h>

#define BB 8
#define NN 4096
#define DD 64
#define SS 1024
#define KK 32
#define CDIM 131   // 64 + 3 + 64

__device__ int g_fps_idx[BB * SS];

// ---------------------------------------------------------------------------
// FPS: one block per batch, 512 threads, 8 points per thread (coords + running
// min-distance kept entirely in registers). Exact no-FMA arithmetic to match
// jnp.sum((xyz - centroid)**2, -1) with accumulation order (dx2+dy2)+dz2.
// argmax tie-break = first (lowest) index, matching jnp.argmax.
// (Verified bit-exact in R2: output 0 passed with rel_err = 0.)
// ---------------------------------------------------------------------------
__global__ __launch_bounds__(512, 1) void fps_kernel(const float* __restrict__ xyz)
{
    const int b    = blockIdx.x;
    const int tid  = threadIdx.x;
    const int lane = tid & 31;
    const int w    = tid >> 5;
    const float* bx = xyz + (size_t)b * NN * 3;

    float px[8], py[8], pz[8], dist[8];
#pragma unroll
    for (int j = 0; j < 8; ++j) {
        int i = tid + j * 512;
        px[j] = bx[i * 3 + 0];
        py[j] = bx[i * 3 + 1];
        pz[j] = bx[i * 3 + 2];
        dist[j] = 10000000000.0f;
    }

    __shared__ float s_val[16];
    __shared__ int   s_idx[16];
    __shared__ int   s_far;

    int far = 0;
    for (int it = 0; it < SS; ++it) {
        if (tid == 0) g_fps_idx[b * SS + it] = far;

        const float cx = __ldg(bx + far * 3 + 0);
        const float cy = __ldg(bx + far * 3 + 1);
        const float cz = __ldg(bx + far * 3 + 2);

        float bv = -1.0f;
        int   bi = 0;
#pragma unroll
        for (int j = 0; j < 8; ++j) {
            float dx = __fadd_rn(px[j], -cx);
            float dy = __fadd_rn(py[j], -cy);
            float dz = __fadd_rn(pz[j], -cz);
            float dd = __fadd_rn(__fadd_rn(__fmul_rn(dx, dx), __fmul_rn(dy, dy)),
                                 __fmul_rn(dz, dz));
            float nd = fminf(dist[j], dd);
            dist[j] = nd;
            // indices ascend with j, so strict > keeps first occurrence
            if (nd > bv) { bv = nd; bi = tid + j * 512; }
        }

        // warp reduction (val, idx), ties -> lower idx
#pragma unroll
        for (int o = 16; o > 0; o >>= 1) {
            float ov = __shfl_down_sync(0xffffffffu, bv, o);
            int   oi = __shfl_down_sync(0xffffffffu, bi, o);
            if (ov > bv || (ov == bv && oi < bi)) { bv = ov; bi = oi; }
        }
        if (lane == 0) { s_val[w] = bv; s_idx[w] = bi; }
        __syncthreads();

        if (w == 0) {
            float v2 = (lane < 16) ? s_val[lane] : -1.0f;
            int   i2 = (lane < 16) ? s_idx[lane] : 0;
#pragma unroll
            for (int o = 8; o > 0; o >>= 1) {
                float ov = __shfl_down_sync(0xffffffffu, v2, o);
                int   oi = __shfl_down_sync(0xffffffffu, i2, o);
                if (ov > v2 || (ov == v2 && oi < i2)) { v2 = ov; i2 = oi; }
            }
            if (lane == 0) s_far = i2;
        }
        __syncthreads();
        far = s_far;
    }
}

// ---------------------------------------------------------------------------
// Fused ball-query + gather. Distance replicates the reference's lowering:
//   dot  = fma(qz,z, fma(qy,y, qx*x))        (GEMM-style FMA accumulation, k asc)
//   nrm  = (x*x + y*y) + z*z                 (square materialized, plain adds)
//   d    = ((-2*dot) + srcn) + dstn          (broadcast-add fusion order)
// ---------------------------------------------------------------------------
__global__ __launch_bounds__(128) void group_kernel(const float* __restrict__ xyz,
                                                    const float* __restrict__ pts,
                                                    float* __restrict__ out_xyz,
                                                    float* __restrict__ out_pts)
{
    const int bs   = blockIdx.x;        // b*S + s
    const int b    = bs >> 10;
    const int tid  = threadIdx.x;
    const int lane = tid & 31;
    const int w    = tid >> 5;

    const float* bx = xyz + (size_t)b * NN * 3;
    const float* pb = pts + (size_t)b * NN * DD;

    const int a = g_fps_idx[bs];
    const float qx = __ldg(bx + a * 3 + 0);
    const float qy = __ldg(bx + a * 3 + 1);
    const float qz = __ldg(bx + a * 3 + 2);
    const float srcn = __fadd_rn(__fadd_rn(__fmul_rn(qx, qx), __fmul_rn(qy, qy)),
                                 __fmul_rn(qz, qz));
    const float r2 = 0.04f;

    __shared__ int seg_buf[4][KK];
    __shared__ int counts[4];
    __shared__ int gidx[KK];

    // ---- ball query: each warp scans its 1024-point segment in index order
    {
        int cnt = 0;
        const int segbase = w * 1024;
        for (int c = 0; c < 32; ++c) {
            int p = segbase + c * 32 + lane;
            float x = __ldg(bx + p * 3 + 0);
            float y = __ldg(bx + p * 3 + 1);
            float z = __ldg(bx + p * 3 + 2);
            // GEMM-style FMA dot, ascending component order
            float dot = __fmaf_rn(qz, z, __fmaf_rn(qy, y, __fmul_rn(qx, x)));
            float dn  = __fadd_rn(__fadd_rn(__fmul_rn(x, x), __fmul_rn(y, y)),
                                  __fmul_rn(z, z));
            float d   = __fadd_rn(__fadd_rn(__fmul_rn(-2.0f, dot), srcn), dn);
            bool hit = !(d > r2);
            unsigned m = __ballot_sync(0xffffffffu, hit);
            if (hit) {
                int r = cnt + __popc(m & ((1u << lane) - 1u));
                if (r < KK) seg_buf[w][r] = p;
            }
            cnt += __popc(m);
            if (cnt >= KK) break;
        }
        if (lane == 0) counts[w] = cnt < KK ? cnt : KK;
    }
    __syncthreads();

    // ---- merge first-32 across segments (threads 0..31)
    if (tid < KK) {
        int c0 = counts[0], c1 = counts[1], c2 = counts[2], c3 = counts[3];
        int o1 = c0, o2 = c0 + c1, o3 = o2 + c2, tot = o3 + c3;
        int w0 = (c0 > 0) ? 0 : ((c1 > 0) ? 1 : ((c2 > 0) ? 2 : 3));
        int g0 = seg_buf[w0][0];
        int j = tid;
        int g;
        if (j < tot) {
            int ws, off;
            if      (j < o1) { ws = 0; off = j; }
            else if (j < o2) { ws = 1; off = j - o1; }
            else if (j < o3) { ws = 2; off = j - o2; }
            else             { ws = 3; off = j - o3; }
            g = seg_buf[ws][off];
        } else {
            g = g0;  // fill with first in-radius index (anchor guarantees >=1 hit)
        }
        gidx[j] = g;
    }
    // new_xyz
    if (tid < 3) out_xyz[(size_t)bs * 3 + tid] = __ldg(bx + a * 3 + tid);
    __syncthreads();

    // ---- gather + concat writes: row = [points[g] (64) | xyz[g] (3) | points[a] (64)]
    float av  = 0.0f, av2 = 0.0f;
    if (tid >= 67) av  = __ldg(pb + (size_t)a * DD + (tid - 67));
    if (tid < 3)   av2 = __ldg(pb + (size_t)a * DD + 61 + tid);   // elems 128..130 -> anchor[61..63]

    float* base0 = out_pts + (size_t)bs * KK * CDIM;
#pragma unroll 4
    for (int k = 0; k < KK; ++k) {
        int g = gidx[k];
        float v;
        if (tid < 64)      v = __ldg(pb + (size_t)g * DD + tid);
        else if (tid < 67) v = __ldg(bx + (size_t)g * 3 + (tid - 64));
        else               v = av;
        float* row = base0 + (size_t)k * CDIM;
        row[tid] = v;
        if (tid < 3) row[128 + tid] = av2;
    }
}

extern "C" void kernel_launch(void* const* d_in, const int* in_sizes, int n_in,
                              void* d_out, int out_size)
{
    const float* xyz = (const float*)d_in[0];   // [B, N, 3]
    const float* pts = (const float*)d_in[1];   // [B, N, D]
    float* out = (float*)d_out;
    float* out_xyz = out;                       // [B, S, 3]
    float* out_pts = out + (size_t)BB * SS * 3; // [B, S, K, 131]

    fps_kernel<<<BB, 512>>>(xyz);
    group_kernel<<<BB * SS, 128>>>(xyz, pts, out_xyz, out_pts);
}